// round 5
// baseline (speedup 1.0000x reference)
#include <cuda_runtime.h>
#include <cstdint>
#include <math.h>

// ---------------------------------------------------------------------------
// Threefry-2x32 (exact JAX implementation: jax/_src/prng.py)
// ---------------------------------------------------------------------------
__host__ __device__ __forceinline__ void threefry2x32(
    unsigned k0, unsigned k1, unsigned x0, unsigned x1,
    unsigned &o0, unsigned &o1)
{
    const unsigned ks2 = k0 ^ k1 ^ 0x1BD11BDAu;
    unsigned a = x0 + k0, b = x1 + k1;
#define TF_ROT(v,d) (((v)<<(d))|((v)>>(32-(d))))
#define TF_R4(r0_,r1_,r2_,r3_) \
    a+=b; b=TF_ROT(b,r0_); b^=a; \
    a+=b; b=TF_ROT(b,r1_); b^=a; \
    a+=b; b=TF_ROT(b,r2_); b^=a; \
    a+=b; b=TF_ROT(b,r3_); b^=a;
    TF_R4(13,15,26, 6);  a+=k1;  b+=ks2+1u;
    TF_R4(17,29,16,24);  a+=ks2; b+=k0 +2u;
    TF_R4(13,15,26, 6);  a+=k0;  b+=k1 +3u;
    TF_R4(17,29,16,24);  a+=k1;  b+=ks2+4u;
    TF_R4(13,15,26, 6);  a+=ks2; b+=k0 +5u;
    o0 = a; o1 = b;
#undef TF_R4
#undef TF_ROT
}

// ---------------------------------------------------------------------------
// Packed fp32x2 helper (sm_103a FFMA2 — 2x FFMA throughput)
// ---------------------------------------------------------------------------
__device__ __forceinline__ unsigned long long fma2(
    unsigned long long a, unsigned long long b, unsigned long long c) {
    unsigned long long d;
    asm("fma.rn.f32x2 %0, %1, %2, %3;" : "=l"(d) : "l"(a), "l"(b), "l"(c));
    return d;
}
__device__ __forceinline__ float ull_lo(unsigned long long v) {
    return __uint_as_float((unsigned)(v & 0xffffffffull));
}
__device__ __forceinline__ float ull_hi(unsigned long long v) {
    return __uint_as_float((unsigned)(v >> 32));
}

// ---------------------------------------------------------------------------
// GEMM: out[T,128] = H[T,D] @ W[D,128], fp32.
// Tile 128x128xBK16, 256 threads, 8x8 micro-tile.
// A packed over adjacent m (pairs), B pre-duplicated in smem -> zero dup-MOVs
// in the inner loop: 32 FFMA2 + 6 LDS per k-step.
// ---------------------------------------------------------------------------
__global__ __launch_bounds__(256, 1)
void gemm128(const float* __restrict__ H, const float* __restrict__ W,
             float* __restrict__ out, int D)
{
    __shared__ float As [16][132];   // transposed h tile (m contiguous)
    __shared__ float Bs2[16][256];   // B with every value duplicated

    const int tid = threadIdx.x;
    const int bm  = blockIdx.x * 128;

    // compute-thread mapping: 16x16 grid
    const int trow = tid >> 4;          // 0..15
    const int tcol = tid & 15;          // 0..15
    const int m0   = trow * 4;          // m: m0..m0+3, m0+64..m0+67
    const int n0   = tcol * 4;          // n: n0..n0+3, n0+64..n0+67

    // load mapping
    const int lrow = tid >> 2;          // 0..63 (A rows; +64 second half)
    const int lkq  = (tid & 3) * 4;     // k offset within BK
    const int bkr  = tid >> 5;          // 0..7  (B k rows; +8 second half)
    const int bc   = (tid & 31) * 4;    // B column

    const float* hPtr = H + (size_t)(bm + lrow) * (size_t)D + lkq;
    const float* wPtr = W + bkr * 128 + bc;

    // acc[mp][nj]: mp = m-pair (0:m0/m0+1, 1:m0+2/3, 2:m0+64/65, 3:m0+66/67)
    //              nj = single n (0..3 -> n0..n0+3, 4..7 -> n0+64..n0+67)
    unsigned long long acc[4][8];
#pragma unroll
    for (int i = 0; i < 4; i++)
#pragma unroll
        for (int j = 0; j < 8; j++) acc[i][j] = 0ull;

    const int nIter = D / 16;

    // preload tile 0
    float4 ra0 = *(const float4*)(hPtr);
    float4 ra1 = *(const float4*)(hPtr + (size_t)64 * D);
    float4 rb0 = *(const float4*)(wPtr);
    float4 rb1 = *(const float4*)(wPtr + 8 * 128);

    for (int it = 0; it < nIter; ++it) {
        // A: transposed scatter
        As[lkq + 0][lrow]      = ra0.x;
        As[lkq + 1][lrow]      = ra0.y;
        As[lkq + 2][lrow]      = ra0.z;
        As[lkq + 3][lrow]      = ra0.w;
        As[lkq + 0][lrow + 64] = ra1.x;
        As[lkq + 1][lrow + 64] = ra1.y;
        As[lkq + 2][lrow + 64] = ra1.z;
        As[lkq + 3][lrow + 64] = ra1.w;
        // B: duplicated pairs
        {
            float4 d;
            d.x = rb0.x; d.y = rb0.x; d.z = rb0.y; d.w = rb0.y;
            *(float4*)&Bs2[bkr][2*bc]     = d;
            d.x = rb0.z; d.y = rb0.z; d.z = rb0.w; d.w = rb0.w;
            *(float4*)&Bs2[bkr][2*bc + 4] = d;
            d.x = rb1.x; d.y = rb1.x; d.z = rb1.y; d.w = rb1.y;
            *(float4*)&Bs2[bkr + 8][2*bc]     = d;
            d.x = rb1.z; d.y = rb1.z; d.z = rb1.w; d.w = rb1.w;
            *(float4*)&Bs2[bkr + 8][2*bc + 4] = d;
        }
        __syncthreads();

        // prefetch next tile into registers
        if (it + 1 < nIter) {
            const float* hp = hPtr + (size_t)(it + 1) * 16;
            ra0 = *(const float4*)(hp);
            ra1 = *(const float4*)(hp + (size_t)64 * D);
            const float* wp = wPtr + (size_t)(it + 1) * 16 * 128;
            rb0 = *(const float4*)(wp);
            rb1 = *(const float4*)(wp + 8 * 128);
        }

#pragma unroll
        for (int k = 0; k < 16; ++k) {
            ulonglong2 la0 = *(const ulonglong2*)&As[k][m0];        // pairs m0/m0+1, m0+2/3
            ulonglong2 la1 = *(const ulonglong2*)&As[k][m0 + 64];   // pairs m0+64/65, 66/67
            ulonglong2 lb0 = *(const ulonglong2*)&Bs2[k][2*n0];          // dup n0, n0+1
            ulonglong2 lb1 = *(const ulonglong2*)&Bs2[k][2*n0 + 4];      // dup n0+2, n0+3
            ulonglong2 lb2 = *(const ulonglong2*)&Bs2[k][2*n0 + 128];    // dup n0+64, n0+65
            ulonglong2 lb3 = *(const ulonglong2*)&Bs2[k][2*n0 + 132];    // dup n0+66, n0+67
            unsigned long long am[4] = { la0.x, la0.y, la1.x, la1.y };
            unsigned long long bn[8] = { lb0.x, lb0.y, lb1.x, lb1.y,
                                         lb2.x, lb2.y, lb3.x, lb3.y };
#pragma unroll
            for (int mp = 0; mp < 4; ++mp)
#pragma unroll
                for (int nj = 0; nj < 8; ++nj)
                    acc[mp][nj] = fma2(am[mp], bn[nj], acc[mp][nj]);
        }
        __syncthreads();
    }

    // writeback: repack pairs into rows, float4 stores
#pragma unroll
    for (int mp = 0; mp < 4; ++mp) {
#pragma unroll
        for (int half = 0; half < 2; ++half) {
            const int m = bm + m0 + ((mp & 1) << 1) + ((mp >> 1) << 6) + half;
            float4 v0, v1;
            if (half == 0) {
                v0.x = ull_lo(acc[mp][0]); v0.y = ull_lo(acc[mp][1]);
                v0.z = ull_lo(acc[mp][2]); v0.w = ull_lo(acc[mp][3]);
                v1.x = ull_lo(acc[mp][4]); v1.y = ull_lo(acc[mp][5]);
                v1.z = ull_lo(acc[mp][6]); v1.w = ull_lo(acc[mp][7]);
            } else {
                v0.x = ull_hi(acc[mp][0]); v0.y = ull_hi(acc[mp][1]);
                v0.z = ull_hi(acc[mp][2]); v0.w = ull_hi(acc[mp][3]);
                v1.x = ull_hi(acc[mp][4]); v1.y = ull_hi(acc[mp][5]);
                v1.z = ull_hi(acc[mp][6]); v1.w = ull_hi(acc[mp][7]);
            }
            *(float4*)&out[(size_t)m * 128 + n0]      = v0;
            *(float4*)&out[(size_t)m * 128 + n0 + 64] = v1;
        }
    }
}

// ---------------------------------------------------------------------------
// Epilogue: one WARP per token (4 tokens per 128-thread CTA).
// Each lane owns 4 experts. No __syncthreads, no smem: butterfly reductions.
// ---------------------------------------------------------------------------
__global__ __launch_bounds__(128)
void router_epilogue(const float* __restrict__ logits,
                     const int* __restrict__ tmask,   // 4-byte bool
                     float* __restrict__ out_mask,
                     float* __restrict__ out_probs,
                     float* __restrict__ out_lsel,
                     unsigned fk0, unsigned fk1)
{
    const int lane = threadIdx.x & 31;
    const int t    = blockIdx.x * 4 + (threadIdx.x >> 5);
    const unsigned base = (unsigned)t * 128u + (unsigned)lane * 4u;

    const float4 l4 = *(const float4*)&logits[base];
    float lc[4] = { l4.x, l4.y, l4.z, l4.w };
    const bool tm = (tmask[t] != 0);

    // --- JAX-exact gumbel (jax_threefry_partitionable=True): bits = o0^o1 ---
    float lsm[4];
#pragma unroll
    for (int j = 0; j < 4; ++j) {
        unsigned o0, o1;
        threefry2x32(fk0, fk1, 0u, base + (unsigned)j, o0, o1);
        const unsigned bits = o0 ^ o1;
        float f = __uint_as_float((bits >> 9) | 0x3f800000u) - 1.0f;
        const float minv = 1e-6f;
        const float maxv = (float)(1.0 - 1e-6);
        float u = fmaxf(minv, f * (maxv - minv) + minv);
        const float g = -logf(-logf(u));
        lsm[j] = tm ? (lc[j] + g) : -INFINITY;
    }

    // --- top-8: iterative warp argmax (ties -> lowest global index) --------
    float v[4] = { lsm[0], lsm[1], lsm[2], lsm[3] };
    bool sel[4] = { false, false, false, false };
#pragma unroll 1
    for (int it = 0; it < 8; ++it) {
        float bv = v[0];
        int   bg = lane * 4;
#pragma unroll
        for (int j = 1; j < 4; ++j)
            if (v[j] > bv) { bv = v[j]; bg = lane * 4 + j; }
#pragma unroll
        for (int off = 16; off; off >>= 1) {
            float ov = __shfl_xor_sync(0xffffffffu, bv, off);
            int   og = __shfl_xor_sync(0xffffffffu, bg, off);
            if (ov > bv || (ov == bv && og < bg)) { bv = ov; bg = og; }
        }
        // all lanes agree on winner bg; owner removes it
#pragma unroll
        for (int j = 0; j < 4; ++j)
            if (bg == lane * 4 + j) { sel[j] = true; v[j] = -INFINITY; }
    }

    // --- softmax over clean logits ----------------------------------------
    float mx = fmaxf(fmaxf(lc[0], lc[1]), fmaxf(lc[2], lc[3]));
#pragma unroll
    for (int off = 16; off; off >>= 1)
        mx = fmaxf(mx, __shfl_xor_sync(0xffffffffu, mx, off));

    float ex[4];
    float s = 0.0f;
#pragma unroll
    for (int j = 0; j < 4; ++j) { ex[j] = expf(lc[j] - mx); s += ex[j]; }
#pragma unroll
    for (int off = 16; off; off >>= 1)
        s += __shfl_xor_sync(0xffffffffu, s, off);

    float p[4];
#pragma unroll
    for (int j = 0; j < 4; ++j) p[j] = tm ? (ex[j] / s) : 0.0f;

    // --- masked renorm -----------------------------------------------------
    float ms = 0.0f;
#pragma unroll
    for (int j = 0; j < 4; ++j) if (sel[j]) ms += p[j];
#pragma unroll
    for (int off = 16; off; off >>= 1)
        ms += __shfl_xor_sync(0xffffffffu, ms, off);
    const float den = fmaxf(ms, 1e-9f);

    float4 omask, oprob, osel;
    float* om = &omask.x; float* op = &oprob.x; float* os = &osel.x;
#pragma unroll
    for (int j = 0; j < 4; ++j) {
        float pr = sel[j] ? (p[j] / den) : 0.0f;
        om[j] = (sel[j] && tm) ? 1.0f : 0.0f;
        op[j] = tm ? pr : 0.0f;
        os[j] = lsm[j];
    }
    *(float4*)&out_mask [base] = omask;
    *(float4*)&out_probs[base] = oprob;
    *(float4*)&out_lsel [base] = osel;
}

// ---------------------------------------------------------------------------
// launch
// ---------------------------------------------------------------------------
extern "C" void kernel_launch(void* const* d_in, const int* in_sizes, int n_in,
                              void* d_out, int out_size)
{
    const float* H  = (const float*)d_in[0];
    const float* W  = (const float*)d_in[1];
    const int*   tm = (const int*)d_in[2];     // bool promoted to 4-byte

    const int T = in_sizes[2];                 // 16384
    const int D = in_sizes[0] / T;             // 4096

    float* outF      = (float*)d_out;
    const unsigned TE = (unsigned)T * 128u;
    float* out_mask  = outF;
    float* out_probs = outF + TE;
    float* out_clean = outF + 2u * TE;
    float* out_sel   = outF + 3u * TE;

    gemm128<<<T / 128, 256>>>(H, W, out_clean, D);

    // folded key: fold_in(key(7), 1) = threefry([0,7], [0,1])
    unsigned fk0, fk1;
    threefry2x32(0u, 7u, 0u, 1u, fk0, fk1);

    router_epilogue<<<T / 4, 128>>>(out_clean, tm, out_mask, out_probs, out_sel,
                                    fk0, fk1);
}

// round 9
// speedup vs baseline: 1.4609x; 1.4609x over previous
#include <cuda_runtime.h>
#include <cuda_bf16.h>
#include <mma.h>
#include <cstdint>
#include <math.h>

using namespace nvcuda;

// ===========================================================================
// Threefry-2x32 (exact JAX)
// ===========================================================================
__host__ __device__ __forceinline__ void threefry2x32(
    unsigned k0, unsigned k1, unsigned x0, unsigned x1,
    unsigned &o0, unsigned &o1)
{
    const unsigned ks2 = k0 ^ k1 ^ 0x1BD11BDAu;
    unsigned a = x0 + k0, b = x1 + k1;
#define TF_ROT(v,d) (((v)<<(d))|((v)>>(32-(d))))
#define TF_R4(r0_,r1_,r2_,r3_) \
    a+=b; b=TF_ROT(b,r0_); b^=a; \
    a+=b; b=TF_ROT(b,r1_); b^=a; \
    a+=b; b=TF_ROT(b,r2_); b^=a; \
    a+=b; b=TF_ROT(b,r3_); b^=a;
    TF_R4(13,15,26, 6);  a+=k1;  b+=ks2+1u;
    TF_R4(17,29,16,24);  a+=ks2; b+=k0 +2u;
    TF_R4(13,15,26, 6);  a+=k0;  b+=k1 +3u;
    TF_R4(17,29,16,24);  a+=k1;  b+=ks2+4u;
    TF_R4(13,15,26, 6);  a+=ks2; b+=k0 +5u;
    o0 = a; o1 = b;
#undef TF_R4
#undef TF_ROT
}

// ===========================================================================
// Static scratch: W transposed + split into 3 bf16 planes [3][E=128][D]
// ===========================================================================
#define MAX_D 4096
__device__ __nv_bfloat16 g_Ws[3u * 128u * MAX_D];

// W[d][e] fp32 -> g_Ws[s][e][d] bf16 (3-way residual split), smem transpose
__global__ void wsplit_kernel(const float* __restrict__ W, int D)
{
    __shared__ float tile[32][33];
    const int d0 = blockIdx.x * 32, e0 = blockIdx.y * 32;
    const int tx = threadIdx.x, ty = threadIdx.y;
#pragma unroll
    for (int i = ty; i < 32; i += 8)
        tile[i][tx] = W[(size_t)(d0 + i) * 128 + e0 + tx];
    __syncthreads();
#pragma unroll
    for (int i = ty; i < 32; i += 8) {
        float a = tile[tx][i];                 // = W[d0+tx][e0+i]
        __nv_bfloat16 b0 = __float2bfloat16(a);
        float r = a - __bfloat162float(b0);
        __nv_bfloat16 b1 = __float2bfloat16(r);
        float r2 = r - __bfloat162float(b1);
        __nv_bfloat16 b2 = __float2bfloat16(r2);
        size_t o = (size_t)(e0 + i) * D + d0 + tx;
        g_Ws[o]                      = b0;
        g_Ws[(size_t)128 * D + o]    = b1;
        g_Ws[(size_t)256 * D + o]    = b2;
    }
}

// ===========================================================================
// GEMM via mma.sync (HMMA) bf16x6-split: out[T,128] = H[T,D] @ W[D,128]
// CTA: 128x128 tile, 256 thr (8 warps, 2x4), warp tile 64x32.
// K-chunk 32, double-buffered smem, 6 planes, rows padded to 40 elems.
// Products: a0b0, a0b1, a0b2, a1b0, a1b1, a2b0.
// RZ-bias correction: flush acc fragments into fp32 RN totals every 4 chunks.
// ===========================================================================
#define CHUNK       32
#define FLUSH_EVERY 4
#define LDP         40                       // padded row length (elems)
#define PLANE_ELEMS (128 * LDP)              // 5120 bf16
#define BUF_ELEMS   (6 * PLANE_ELEMS)        // 30720 bf16 = 61440 B
#define SMEM_BYTES  (2 * BUF_ELEMS * 2)      // 122880 B

__global__ __launch_bounds__(256, 1)
void gemm_mma(const float* __restrict__ H, float* __restrict__ out, int D)
{
    extern __shared__ __nv_bfloat16 sm[];
    const int tid  = threadIdx.x;
    const int wid  = tid >> 5;
    const int bm   = blockIdx.x * 128;
    const int row  = tid >> 1;          // 0..127 (token row / expert row)
    const int half = tid & 1;           // 16-elem half of the 32-elem chunk
    const int wm   = (wid >> 2) * 64;   // warp m offset
    const int wn   = (wid & 3) * 32;    // warp n offset

    wmma::fragment<wmma::accumulator, 16, 16, 16, float> acc[4][2];
    float tot[4][2][8];
#pragma unroll
    for (int mi = 0; mi < 4; ++mi)
#pragma unroll
        for (int nj = 0; nj < 2; ++nj) {
            wmma::fill_fragment(acc[mi][nj], 0.0f);
#pragma unroll
            for (int i = 0; i < 8; ++i) tot[mi][nj][i] = 0.0f;
        }

    const int nch = D / CHUNK;

    // prefetch registers
    float4 h4[4];
    uint4  wv[3][2];

    // ---- LDG chunk 0 ------------------------------------------------------
    {
        const float4* hp = (const float4*)(H + (size_t)(bm + row) * D + half * 16);
        h4[0] = hp[0]; h4[1] = hp[1]; h4[2] = hp[2]; h4[3] = hp[3];
#pragma unroll
        for (int s = 0; s < 3; ++s) {
            const uint4* wp = (const uint4*)(g_Ws + (size_t)s * 128 * D
                                             + (size_t)row * D + half * 16);
            wv[s][0] = wp[0]; wv[s][1] = wp[1];
        }
    }

    for (int c = 0; c < nch; ++c) {
        const int b = c & 1;
        __nv_bfloat16* buf = sm + b * BUF_ELEMS;

        // ---- STS: split H to 3 planes, copy W planes ----------------------
        {
            float v[16] = { h4[0].x, h4[0].y, h4[0].z, h4[0].w,
                            h4[1].x, h4[1].y, h4[1].z, h4[1].w,
                            h4[2].x, h4[2].y, h4[2].z, h4[2].w,
                            h4[3].x, h4[3].y, h4[3].z, h4[3].w };
            uint32_t q0[8], q1[8], q2[8];
#pragma unroll
            for (int j = 0; j < 8; ++j) {
                float x0 = v[2*j], x1 = v[2*j+1];
                __nv_bfloat16 a0 = __float2bfloat16(x0);
                __nv_bfloat16 c0 = __float2bfloat16(x1);
                float r0 = x0 - __bfloat162float(a0);
                float r1 = x1 - __bfloat162float(c0);
                __nv_bfloat16 a1 = __float2bfloat16(r0);
                __nv_bfloat16 c1 = __float2bfloat16(r1);
                float t0 = r0 - __bfloat162float(a1);
                float t1 = r1 - __bfloat162float(c1);
                __nv_bfloat16 a2 = __float2bfloat16(t0);
                __nv_bfloat16 c2 = __float2bfloat16(t1);
                q0[j] = ((uint32_t)__bfloat16_as_ushort(c0) << 16) | __bfloat16_as_ushort(a0);
                q1[j] = ((uint32_t)__bfloat16_as_ushort(c1) << 16) | __bfloat16_as_ushort(a1);
                q2[j] = ((uint32_t)__bfloat16_as_ushort(c2) << 16) | __bfloat16_as_ushort(a2);
            }
            const int off = row * LDP + half * 16;
            *(uint4*)(buf + 0*PLANE_ELEMS + off)     = make_uint4(q0[0], q0[1], q0[2], q0[3]);
            *(uint4*)(buf + 0*PLANE_ELEMS + off + 8) = make_uint4(q0[4], q0[5], q0[6], q0[7]);
            *(uint4*)(buf + 1*PLANE_ELEMS + off)     = make_uint4(q1[0], q1[1], q1[2], q1[3]);
            *(uint4*)(buf + 1*PLANE_ELEMS + off + 8) = make_uint4(q1[4], q1[5], q1[6], q1[7]);
            *(uint4*)(buf + 2*PLANE_ELEMS + off)     = make_uint4(q2[0], q2[1], q2[2], q2[3]);
            *(uint4*)(buf + 2*PLANE_ELEMS + off + 8) = make_uint4(q2[4], q2[5], q2[6], q2[7]);
#pragma unroll
            for (int s = 0; s < 3; ++s) {
                *(uint4*)(buf + (3+s)*PLANE_ELEMS + off)     = wv[s][0];
                *(uint4*)(buf + (3+s)*PLANE_ELEMS + off + 8) = wv[s][1];
            }
        }
        __syncthreads();

        // ---- prefetch next chunk into registers ---------------------------
        if (c + 1 < nch) {
            const float4* hp = (const float4*)(H + (size_t)(bm + row) * D
                                               + (size_t)(c + 1) * CHUNK + half * 16);
            h4[0] = hp[0]; h4[1] = hp[1]; h4[2] = hp[2]; h4[3] = hp[3];
#pragma unroll
            for (int s = 0; s < 3; ++s) {
                const uint4* wp = (const uint4*)(g_Ws + (size_t)s * 128 * D
                                                 + (size_t)row * D
                                                 + (size_t)(c + 1) * CHUNK + half * 16);
                wv[s][0] = wp[0]; wv[s][1] = wp[1];
            }
        }

        // ---- compute: 6 products x 2 k16 steps ----------------------------
#pragma unroll
        for (int ks = 0; ks < 2; ++ks) {
            const int k0 = ks * 16;
            wmma::fragment<wmma::matrix_b, 16, 16, 16, __nv_bfloat16, wmma::col_major> bfr[3][2];
#pragma unroll
            for (int s = 0; s < 3; ++s)
#pragma unroll
                for (int nj = 0; nj < 2; ++nj)
                    wmma::load_matrix_sync(bfr[s][nj],
                        buf + (3+s)*PLANE_ELEMS + (wn + nj*16) * LDP + k0, LDP);

            wmma::fragment<wmma::matrix_a, 16, 16, 16, __nv_bfloat16, wmma::row_major> afr[4];

            // pa = 0 : pb in {0,1,2}
#pragma unroll
            for (int mi = 0; mi < 4; ++mi)
                wmma::load_matrix_sync(afr[mi],
                    buf + 0*PLANE_ELEMS + (wm + mi*16) * LDP + k0, LDP);
#pragma unroll
            for (int mi = 0; mi < 4; ++mi)
#pragma unroll
                for (int nj = 0; nj < 2; ++nj) {
                    wmma::mma_sync(acc[mi][nj], afr[mi], bfr[0][nj], acc[mi][nj]);
                    wmma::mma_sync(acc[mi][nj], afr[mi], bfr[1][nj], acc[mi][nj]);
                    wmma::mma_sync(acc[mi][nj], afr[mi], bfr[2][nj], acc[mi][nj]);
                }

            // pa = 1 : pb in {0,1}
#pragma unroll
            for (int mi = 0; mi < 4; ++mi)
                wmma::load_matrix_sync(afr[mi],
                    buf + 1*PLANE_ELEMS + (wm + mi*16) * LDP + k0, LDP);
#pragma unroll
            for (int mi = 0; mi < 4; ++mi)
#pragma unroll
                for (int nj = 0; nj < 2; ++nj) {
                    wmma::mma_sync(acc[mi][nj], afr[mi], bfr[0][nj], acc[mi][nj]);
                    wmma::mma_sync(acc[mi][nj], afr[mi], bfr[1][nj], acc[mi][nj]);
                }

            // pa = 2 : pb = 0
#pragma unroll
            for (int mi = 0; mi < 4; ++mi)
                wmma::load_matrix_sync(afr[mi],
                    buf + 2*PLANE_ELEMS + (wm + mi*16) * LDP + k0, LDP);
#pragma unroll
            for (int mi = 0; mi < 4; ++mi)
#pragma unroll
                for (int nj = 0; nj < 2; ++nj)
                    wmma::mma_sync(acc[mi][nj], afr[mi], bfr[0][nj], acc[mi][nj]);
        }

        // ---- flush: drain RZ-biased fragment accumulators into RN fp32 ----
        if ((c & (FLUSH_EVERY - 1)) == (FLUSH_EVERY - 1)) {
#pragma unroll
            for (int mi = 0; mi < 4; ++mi)
#pragma unroll
                for (int nj = 0; nj < 2; ++nj)
#pragma unroll
                    for (int i = 0; i < 8; ++i) {
                        tot[mi][nj][i] += acc[mi][nj].x[i];
                        acc[mi][nj].x[i] = 0.0f;
                    }
        }
    }

    // ---- writeback: copy totals back into fragments, store ----------------
#pragma unroll
    for (int mi = 0; mi < 4; ++mi)
#pragma unroll
        for (int nj = 0; nj < 2; ++nj) {
#pragma unroll
            for (int i = 0; i < 8; ++i)
                acc[mi][nj].x[i] = tot[mi][nj][i] + acc[mi][nj].x[i];
            wmma::store_matrix_sync(out + (size_t)(bm + wm + mi*16) * 128 + wn + nj*16,
                                    acc[mi][nj], 128, wmma::mem_row_major);
        }
}

// ===========================================================================
// Epilogue: one WARP per token (measured 26us)
// ===========================================================================
__global__ __launch_bounds__(128)
void router_epilogue(const float* __restrict__ logits,
                     const int* __restrict__ tmask,
                     float* __restrict__ out_mask,
                     float* __restrict__ out_probs,
                     float* __restrict__ out_lsel,
                     unsigned fk0, unsigned fk1)
{
    const int lane = threadIdx.x & 31;
    const int t    = blockIdx.x * 4 + (threadIdx.x >> 5);
    const unsigned base = (unsigned)t * 128u + (unsigned)lane * 4u;

    const float4 l4 = *(const float4*)&logits[base];
    float lc[4] = { l4.x, l4.y, l4.z, l4.w };
    const bool tm = (tmask[t] != 0);

    float lsm[4];
#pragma unroll
    for (int j = 0; j < 4; ++j) {
        unsigned o0, o1;
        threefry2x32(fk0, fk1, 0u, base + (unsigned)j, o0, o1);
        const unsigned bits = o0 ^ o1;
        float f = __uint_as_float((bits >> 9) | 0x3f800000u) - 1.0f;
        const float minv = 1e-6f;
        const float maxv = (float)(1.0 - 1e-6);
        float u = fmaxf(minv, f * (maxv - minv) + minv);
        const float g = -logf(-logf(u));
        lsm[j] = tm ? (lc[j] + g) : -INFINITY;
    }

    float v[4] = { lsm[0], lsm[1], lsm[2], lsm[3] };
    bool sel[4] = { false, false, false, false };
#pragma unroll 1
    for (int it = 0; it < 8; ++it) {
        float bv = v[0];
        int   bg = lane * 4;
#pragma unroll
        for (int j = 1; j < 4; ++j)
            if (v[j] > bv) { bv = v[j]; bg = lane * 4 + j; }
#pragma unroll
        for (int off = 16; off; off >>= 1) {
            float ov = __shfl_xor_sync(0xffffffffu, bv, off);
            int   og = __shfl_xor_sync(0xffffffffu, bg, off);
            if (ov > bv || (ov == bv && og < bg)) { bv = ov; bg = og; }
        }
#pragma unroll
        for (int j = 0; j < 4; ++j)
            if (bg == lane * 4 + j) { sel[j] = true; v[j] = -INFINITY; }
    }

    float mx = fmaxf(fmaxf(lc[0], lc[1]), fmaxf(lc[2], lc[3]));
#pragma unroll
    for (int off = 16; off; off >>= 1)
        mx = fmaxf(mx, __shfl_xor_sync(0xffffffffu, mx, off));

    float ex[4];
    float s = 0.0f;
#pragma unroll
    for (int j = 0; j < 4; ++j) { ex[j] = expf(lc[j] - mx); s += ex[j]; }
#pragma unroll
    for (int off = 16; off; off >>= 1)
        s += __shfl_xor_sync(0xffffffffu, s, off);

    float p[4];
#pragma unroll
    for (int j = 0; j < 4; ++j) p[j] = tm ? (ex[j] / s) : 0.0f;

    float ms = 0.0f;
#pragma unroll
    for (int j = 0; j < 4; ++j) if (sel[j]) ms += p[j];
#pragma unroll
    for (int off = 16; off; off >>= 1)
        ms += __shfl_xor_sync(0xffffffffu, ms, off);
    const float den = fmaxf(ms, 1e-9f);

    float4 omask, oprob, osel;
    float* om = &omask.x; float* op = &oprob.x; float* os = &osel.x;
#pragma unroll
    for (int j = 0; j < 4; ++j) {
        float pr = sel[j] ? (p[j] / den) : 0.0f;
        om[j] = (sel[j] && tm) ? 1.0f : 0.0f;
        op[j] = tm ? pr : 0.0f;
        os[j] = lsm[j];
    }
    *(float4*)&out_mask [base] = omask;
    *(float4*)&out_probs[base] = oprob;
    *(float4*)&out_lsel [base] = osel;
}

// ===========================================================================
// launch
// ===========================================================================
extern "C" void kernel_launch(void* const* d_in, const int* in_sizes, int n_in,
                              void* d_out, int out_size)
{
    const float* H  = (const float*)d_in[0];
    const float* W  = (const float*)d_in[1];
    const int*   tm = (const int*)d_in[2];

    const int T = in_sizes[2];                 // 16384
    const int D = in_sizes[0] / T;             // 4096

    float* outF      = (float*)d_out;
    const unsigned TE = (unsigned)T * 128u;
    float* out_mask  = outF;
    float* out_probs = outF + TE;
    float* out_clean = outF + 2u * TE;
    float* out_sel   = outF + 3u * TE;

    cudaFuncSetAttribute(gemm_mma, cudaFuncAttributeMaxDynamicSharedMemorySize,
                         SMEM_BYTES);

    wsplit_kernel<<<dim3(D / 32, 4), dim3(32, 8)>>>(W, D);
    gemm_mma<<<T / 128, 256, SMEM_BYTES>>>(H, out_clean, D);

    unsigned fk0, fk1;
    threefry2x32(0u, 7u, 0u, 1u, fk0, fk1);

    router_epilogue<<<T / 4, 128>>>(out_clean, tm, out_mask, out_probs, out_sel,
                                    fk0, fk1);
}